// round 7
// baseline (speedup 1.0000x reference)
#include <cuda_runtime.h>
#include <math.h>

#define N_NODES 100000
#define N_EDGES 3200000
#define D_IN    128
#define D_HID   16
#define D_OUT   2
#define NBLK    ((N_NODES + 255) / 256)   // 391 scan blocks

// ---------------- constant weights ----------------
__constant__ float cW1[D_IN * D_HID];
__constant__ float cW2[D_HID * D_OUT];
__constant__ float cb1[D_HID];
__constant__ float cb2[D_OUT];

// ---------------- scratch ----------------
__device__ float g_h1   [N_NODES * D_HID];  // (x @ W1) * dinv
__device__ float g_g2   [N_NODES * D_OUT];  // (h2 @ W2) * dinv
__device__ float g_dinv [N_NODES];
__device__ int   g_count[N_NODES];          // in-degree (no self loop)
__device__ int   g_off  [N_NODES + 1];      // CSR row offsets (by dst)
__device__ int   g_cur  [N_NODES];          // scatter cursors
__device__ int   g_csrc [N_EDGES];          // CSR: src ids grouped by dst
__device__ int   g_bsum [NBLK];
__device__ int   g_bpre [NBLK];

// ---------------- init ----------------
__global__ void init_kernel() {
    int i = blockIdx.x * blockDim.x + threadIdx.x;
    if (i < N_NODES) g_count[i] = 0;
    if (i == 0) g_off[N_NODES] = N_EDGES;
}

// ---------------- histogram over dst ----------------
__global__ void deg_kernel(const int* __restrict__ ei) {
    int e = blockIdx.x * blockDim.x + threadIdx.x;
    if (e >= N_EDGES) return;
    atomicAdd(&g_count[ei[N_EDGES + e]], 1);
}

__global__ void dinv_kernel() {
    int i = blockIdx.x * blockDim.x + threadIdx.x;
    if (i < N_NODES) g_dinv[i] = rsqrtf((float)(g_count[i] + 1));
}

// ---------------- scan step 1: per-block sums ----------------
__global__ void bsum_kernel() {
    __shared__ int s[256];
    int t = threadIdx.x;
    int i = blockIdx.x * 256 + t;
    s[t] = (i < N_NODES) ? g_count[i] : 0;
    __syncthreads();
    for (int d = 128; d > 0; d >>= 1) {
        if (t < d) s[t] += s[t + d];
        __syncthreads();
    }
    if (t == 0) g_bsum[blockIdx.x] = s[0];
}

// ---------------- scan step 2: single-block scan of block sums ----------------
__global__ void bscan_kernel() {
    __shared__ int s[512];
    int t = threadIdx.x;
    int v = (t < NBLK) ? g_bsum[t] : 0;
    s[t] = v;
    __syncthreads();
    for (int d = 1; d < 512; d <<= 1) {
        int u = (t >= d) ? s[t - d] : 0;
        __syncthreads();
        s[t] += u;
        __syncthreads();
    }
    if (t < NBLK) g_bpre[t] = s[t] - v;   // exclusive
}

// ---------------- scan step 3: per-block offsets ----------------
__global__ void offsets_kernel() {
    __shared__ int s[256];
    int t = threadIdx.x;
    int i = blockIdx.x * 256 + t;
    int v = (i < N_NODES) ? g_count[i] : 0;
    s[t] = v;
    __syncthreads();
    for (int d = 1; d < 256; d <<= 1) {
        int u = (t >= d) ? s[t - d] : 0;
        __syncthreads();
        s[t] += u;
        __syncthreads();
    }
    if (i < N_NODES) {
        int off = g_bpre[blockIdx.x] + s[t] - v;   // exclusive scan
        g_off[i] = off;
        g_cur[i] = off;
    }
}

// ---------------- scatter: build CSR ----------------
__global__ void scatter_kernel(const int* __restrict__ ei) {
    int e = blockIdx.x * blockDim.x + threadIdx.x;
    if (e >= N_EDGES) return;
    int s = ei[e];
    int d = ei[N_EDGES + e];
    int pos = atomicAdd(&g_cur[d], 1);
    g_csrc[pos] = s;
}

// ---------------- GEMM1: 4 threads per node ----------------
__global__ void __launch_bounds__(256) gemm1_kernel(const float* __restrict__ x) {
    int gt = blockIdx.x * 256 + threadIdx.x;
    int node = gt >> 2;
    int q    = gt & 3;
    if (node >= N_NODES) return;
    const float4* xr = (const float4*)(x + (size_t)node * D_IN);

    float acc[D_HID];
#pragma unroll
    for (int j = 0; j < D_HID; j++) acc[j] = 0.0f;

#pragma unroll 8
    for (int i = 0; i < 8; i++) {            // 8 float4 per thread
        int k4 = q * 8 + i;
        float4 xv = xr[k4];
        float xs[4] = {xv.x, xv.y, xv.z, xv.w};
#pragma unroll
        for (int kk = 0; kk < 4; kk++) {
            const float* w = &cW1[(k4 * 4 + kk) * D_HID];
#pragma unroll
            for (int j = 0; j < D_HID; j++)
                acc[j] = fmaf(xs[kk], w[j], acc[j]);
        }
    }
    // combine 4 partial threads (xor 1, xor 2)
#pragma unroll
    for (int j = 0; j < D_HID; j++)
        acc[j] += __shfl_xor_sync(0xFFFFFFFF, acc[j], 1);
#pragma unroll
    for (int j = 0; j < D_HID; j++)
        acc[j] += __shfl_xor_sync(0xFFFFFFFF, acc[j], 2);

    const float di = g_dinv[node];
    float4 o = make_float4(acc[q * 4 + 0] * di, acc[q * 4 + 1] * di,
                           acc[q * 4 + 2] * di, acc[q * 4 + 3] * di);
    *(float4*)&g_h1[(size_t)node * D_HID + q * 4] = o;
}

// ------- fused layer-1 aggregation + relu + W2 projection (warp per node) -------
__global__ void __launch_bounds__(256) agg1_kernel() {
    int warp = (blockIdx.x * 256 + threadIdx.x) >> 5;
    if (warp >= N_NODES) return;
    int lane  = threadIdx.x & 31;
    int sub   = lane & 3;      // feature quad 0..3
    int eslot = lane >> 2;     // 8 edge slots

    int start = g_off[warp];
    int end   = g_off[warp + 1];

    float4 acc = make_float4(0.f, 0.f, 0.f, 0.f);
    for (int i = start + eslot; i < end; i += 8) {
        int s = g_csrc[i];
        float4 v = *(const float4*)&g_h1[(size_t)s * D_HID + sub * 4];
        acc.x += v.x; acc.y += v.y; acc.z += v.z; acc.w += v.w;
    }
    // reduce across 8 edge slots (lanes stride 4)
#pragma unroll
    for (int d = 4; d < 32; d <<= 1) {
        acc.x += __shfl_xor_sync(0xFFFFFFFF, acc.x, d);
        acc.y += __shfl_xor_sync(0xFFFFFFFF, acc.y, d);
        acc.z += __shfl_xor_sync(0xFFFFFFFF, acc.z, d);
        acc.w += __shfl_xor_sync(0xFFFFFFFF, acc.w, d);
    }
    // self loop + norm + bias + relu + W2
    float di = g_dinv[warp];
    float4 h = *(const float4*)&g_h1[(size_t)warp * D_HID + sub * 4];
    float hv[4] = {acc.x + h.x, acc.y + h.y, acc.z + h.z, acc.w + h.w};
    float z0 = 0.f, z1 = 0.f;
#pragma unroll
    for (int k = 0; k < 4; k++) {
        int j = sub * 4 + k;
        float h2 = fmaxf(fmaf(di, hv[k], cb1[j]), 0.f);
        z0 = fmaf(h2, cW2[j * D_OUT + 0], z0);
        z1 = fmaf(h2, cW2[j * D_OUT + 1], z1);
    }
    // reduce across the 4 feature quads
#pragma unroll
    for (int d = 1; d < 4; d <<= 1) {
        z0 += __shfl_xor_sync(0xFFFFFFFF, z0, d);
        z1 += __shfl_xor_sync(0xFFFFFFFF, z1, d);
    }
    if (lane == 0) {
        g_g2[warp * 2 + 0] = z0 * di;
        g_g2[warp * 2 + 1] = z1 * di;
    }
}

// ------- fused layer-2 aggregation + log_softmax (warp per node) -------
__global__ void __launch_bounds__(256) agg2_kernel(float* __restrict__ out) {
    int warp = (blockIdx.x * 256 + threadIdx.x) >> 5;
    if (warp >= N_NODES) return;
    int lane = threadIdx.x & 31;

    int start = g_off[warp];
    int end   = g_off[warp + 1];

    float a0 = 0.f, a1 = 0.f;
    for (int i = start + lane; i < end; i += 32) {
        int s = g_csrc[i];
        float2 m = *(const float2*)&g_g2[s * 2];
        a0 += m.x; a1 += m.y;
    }
#pragma unroll
    for (int d = 1; d < 32; d <<= 1) {
        a0 += __shfl_xor_sync(0xFFFFFFFF, a0, d);
        a1 += __shfl_xor_sync(0xFFFFFFFF, a1, d);
    }
    if (lane == 0) {
        float di = g_dinv[warp];
        float z0 = fmaf(di, a0 + g_g2[warp * 2 + 0], cb2[0]);
        float z1 = fmaf(di, a1 + g_g2[warp * 2 + 1], cb2[1]);
        float m  = fmaxf(z0, z1);
        float lse = m + logf(expf(z0 - m) + expf(z1 - m));
        out[warp * 2 + 0] = z0 - lse;
        out[warp * 2 + 1] = z1 - lse;
    }
}

// ---------------- launch ----------------
extern "C" void kernel_launch(void* const* d_in, const int* in_sizes, int n_in,
                              void* d_out, int out_size) {
    const float* x  = (const float*)d_in[0];
    const float* W1 = (const float*)d_in[1];
    const float* b1 = (const float*)d_in[2];
    const float* W2 = (const float*)d_in[3];
    const float* b2 = (const float*)d_in[4];
    const int*   ei = (const int*)d_in[5];
    float* out = (float*)d_out;

    cudaMemcpyToSymbolAsync(cW1, W1, D_IN * D_HID * sizeof(float), 0, cudaMemcpyDeviceToDevice);
    cudaMemcpyToSymbolAsync(cW2, W2, D_HID * D_OUT * sizeof(float), 0, cudaMemcpyDeviceToDevice);
    cudaMemcpyToSymbolAsync(cb1, b1, D_HID * sizeof(float), 0, cudaMemcpyDeviceToDevice);
    cudaMemcpyToSymbolAsync(cb2, b2, D_OUT * sizeof(float), 0, cudaMemcpyDeviceToDevice);

    const int T = 256;
    init_kernel<<<(N_NODES + T - 1) / T, T>>>();
    deg_kernel<<<(N_EDGES + T - 1) / T, T>>>(ei);
    dinv_kernel<<<(N_NODES + T - 1) / T, T>>>();
    bsum_kernel<<<NBLK, 256>>>();
    bscan_kernel<<<1, 512>>>();
    offsets_kernel<<<NBLK, 256>>>();
    scatter_kernel<<<(N_EDGES + T - 1) / T, T>>>(ei);
    gemm1_kernel<<<(N_NODES * 4 + 255) / 256, 256>>>(x);
    agg1_kernel<<<(N_NODES * 32 + 255) / 256, 256>>>();
    agg2_kernel<<<(N_NODES * 32 + 255) / 256, 256>>>(out);
}